// round 6
// baseline (speedup 1.0000x reference)
#include <cuda_runtime.h>
#include <cuda_bf16.h>

#define N_NODES 32768
#define N_EDGES 160000
#define DIM     768
#define N_REL   3
#define H1      4
#define O1      192
#define H2      1
#define O2      768

// ---- mma GEMM tiling ----
#define MT 128
#define NT 256
#define KC 32
#define NCHUNK (DIM / KC)       // 24
#define NSTAGE 4
#define ST_A 0                  // A: 128 rows x 128B (hi|lo packed)
#define ST_B 16384              // B: 256 rows x 128B
#define STAGE_SZ 49152
#define SMEM_TOTAL (NSTAGE * STAGE_SZ)   // 196608

// ---------------- scratch ----------------
__device__ float g_xr[(size_t)N_REL * N_NODES * DIM];
__device__ float g_h [(size_t)N_NODES * DIM];
__device__ float g_Q [N_REL * N_NODES * H1];
__device__ float g_K [N_REL * N_NODES * H1];
__device__ float g_alpha[N_EDGES * H1];
__device__ int   g_src[N_EDGES], g_dst[N_EDGES], g_et[N_EDGES];
__device__ int   g_deg[N_NODES];
__device__ int   g_off[N_NODES + 1];
__device__ int   g_pos[N_NODES];
__device__ int   g_eperm[N_EDGES];
__device__ __align__(16) __nv_bfloat16 g_Ahi[(size_t)N_NODES * DIM];
__device__ __align__(16) __nv_bfloat16 g_Alo[(size_t)N_NODES * DIM];
__device__ __align__(16) __nv_bfloat16 g_Bthi[(size_t)N_REL * DIM * DIM];  // [r][n][d]
__device__ __align__(16) __nv_bfloat16 g_Btlo[(size_t)N_REL * DIM * DIM];

// ---------------- PTX helpers ----------------
__device__ __forceinline__ unsigned smem_u32(const void* p) {
    unsigned a;
    asm("{ .reg .u64 t; cvta.to.shared.u64 t, %1; cvt.u32.u64 %0, t; }" : "=r"(a) : "l"(p));
    return a;
}
__device__ __forceinline__ void cp16(unsigned d, const void* s) {
    asm volatile("cp.async.cg.shared.global [%0], [%1], 16;" :: "r"(d), "l"(s));
}
__device__ __forceinline__ unsigned sw128(unsigned o) { return o ^ ((o >> 3) & 0x70); }

__device__ __forceinline__ void ldsm4(unsigned* r, unsigned addr) {
    asm volatile("ldmatrix.sync.aligned.m8n8.x4.shared.b16 {%0,%1,%2,%3}, [%4];"
                 : "=r"(r[0]), "=r"(r[1]), "=r"(r[2]), "=r"(r[3]) : "r"(addr));
}
__device__ __forceinline__ void mma16816(float* c, const unsigned* a, const unsigned* b) {
    asm volatile(
        "mma.sync.aligned.m16n8k16.row.col.f32.bf16.bf16.f32 "
        "{%0,%1,%2,%3}, {%4,%5,%6,%7}, {%8,%9}, {%0,%1,%2,%3};"
        : "+f"(c[0]), "+f"(c[1]), "+f"(c[2]), "+f"(c[3])
        : "r"(a[0]), "r"(a[1]), "r"(a[2]), "r"(a[3]), "r"(b[0]), "r"(b[1]));
}

// ---------------- edge preprocessing (known-correct) ----------------
__global__ void k_zero_deg() {
    int i = blockIdx.x * blockDim.x + threadIdx.x;
    if (i < N_NODES) g_deg[i] = 0;
}
__global__ void k_prep_edges(const int* __restrict__ ei, const int* __restrict__ et) {
    int e = blockIdx.x * blockDim.x + threadIdx.x;
    if (e >= N_EDGES) return;
    int s = ei[e] & (N_NODES - 1);
    int d = ei[N_EDGES + e] & (N_NODES - 1);
    int t = et[e];
    t = (t < 0) ? 0 : (t >= N_REL ? N_REL - 1 : t);
    g_src[e] = s; g_dst[e] = d; g_et[e] = t;
    atomicAdd(&g_deg[d], 1);
}
__global__ void k_scan() {
    __shared__ int ps[1024];
    int tid = threadIdx.x, base = tid * 32, local[32], s = 0;
#pragma unroll
    for (int j = 0; j < 32; j++) { local[j] = g_deg[base + j]; s += local[j]; }
    ps[tid] = s;
    __syncthreads();
    for (int st = 1; st < 1024; st <<= 1) {
        int v = (tid >= st) ? ps[tid - st] : 0;
        __syncthreads(); ps[tid] += v; __syncthreads();
    }
    int run = ps[tid] - s;
#pragma unroll
    for (int j = 0; j < 32; j++) { g_off[base + j] = run; g_pos[base + j] = run; run += local[j]; }
    if (tid == 1023) g_off[N_NODES] = run;
}
__global__ void k_scatter() {
    int e = blockIdx.x * blockDim.x + threadIdx.x;
    if (e >= N_EDGES) return;
    int p = atomicAdd(&g_pos[g_dst[e]], 1);
    g_eperm[p] = e;
}

// ---------------- bf16 hi/lo split of A (x or g_h) ----------------
template <bool FROM_H>
__global__ void k_splitA(const float4* __restrict__ in_x) {
    const float4* in = FROM_H ? (const float4*)g_h : in_x;
    int i = blockIdx.x * blockDim.x + threadIdx.x;
    float4 v = in[i];
    __nv_bfloat16 h0 = __float2bfloat16(v.x), h1 = __float2bfloat16(v.y),
                  h2 = __float2bfloat16(v.z), h3 = __float2bfloat16(v.w);
    __nv_bfloat16 l0 = __float2bfloat16(v.x - __bfloat162float(h0));
    __nv_bfloat16 l1 = __float2bfloat16(v.y - __bfloat162float(h1));
    __nv_bfloat16 l2 = __float2bfloat16(v.z - __bfloat162float(h2));
    __nv_bfloat16 l3 = __float2bfloat16(v.w - __bfloat162float(h3));
    ((__nv_bfloat162*)g_Ahi)[2 * i]     = __nv_bfloat162(h0, h1);
    ((__nv_bfloat162*)g_Ahi)[2 * i + 1] = __nv_bfloat162(h2, h3);
    ((__nv_bfloat162*)g_Alo)[2 * i]     = __nv_bfloat162(l0, l1);
    ((__nv_bfloat162*)g_Alo)[2 * i + 1] = __nv_bfloat162(l2, l3);
}

// ---------------- transpose + split W -> Bt [r][n][d] ----------------
__global__ void k_splitW(const float* __restrict__ W) {
    __shared__ float tile[32][33];
    int r = blockIdx.z, d0 = blockIdx.y * 32, f0 = blockIdx.x * 32;
    int tx = threadIdx.x, ty = threadIdx.y;
    const float* Wr = W + (size_t)r * DIM * DIM;
#pragma unroll
    for (int j = 0; j < 32; j += 8)
        tile[ty + j][tx] = Wr[(size_t)(d0 + ty + j) * DIM + f0 + tx];
    __syncthreads();
#pragma unroll
    for (int j = 0; j < 32; j += 8) {
        int n = f0 + ty + j, d = d0 + tx;
        float v = tile[tx][ty + j];
        __nv_bfloat16 h = __float2bfloat16(v);
        __nv_bfloat16 l = __float2bfloat16(v - __bfloat162float(h));
        size_t o = ((size_t)r * DIM + n) * DIM + d;
        g_Bthi[o] = h;
        g_Btlo[o] = l;
    }
}

// ---------------- HMMA GEMM: g_xr[r] = A @ Bt[r]^T ----------------
// SMEM stage layout: A rows 0..127: [hi(64B) | lo(64B)] per row (128B, SW128)
//                    B rows 0..255: same packing.
__device__ __forceinline__ void load_chunk(unsigned stg, int k0,
        const __nv_bfloat16* aH, const __nv_bfloat16* aL,
        const __nv_bfloat16* bH, const __nv_bfloat16* bL, int t) {
    {   // A: 128 rows x 4 units (hi) + 4 units (lo); 512 threads -> 1 unit each
        int row = t >> 2, kc = t & 3;
        size_t go = (size_t)row * DIM + k0 + kc * 8;
        cp16(stg + ST_A + sw128(row * 128 + kc * 16), aH + go);
        cp16(stg + ST_A + sw128(row * 128 + 64 + kc * 16), aL + go);
    }
#pragma unroll
    for (int j = 0; j < 2; j++) {   // B: 256 rows x 4 units each for hi and lo
        int u = j * 512 + t;
        int row = u >> 2, kc = u & 3;
        size_t go = (size_t)row * DIM + k0 + kc * 8;
        cp16(stg + ST_B + sw128(row * 128 + kc * 16), bH + go);
        cp16(stg + ST_B + sw128(row * 128 + 64 + kc * 16), bL + go);
    }
}

__global__ __launch_bounds__(512, 1) void k_gemm_mma() {
    extern __shared__ char smem[];
    unsigned sb = smem_u32(smem);
    int t = threadIdx.x, wid = t >> 5, lane = t & 31;
    int wm = wid & 3, wn = wid >> 2;            // 4(m) x 4(n) warps; warp tile 32x64
    int nt3 = blockIdx.x % 3, r = blockIdx.x / 3;
    int bm = blockIdx.y * MT, bn = nt3 * NT;

    const __nv_bfloat16* aH = g_Ahi + (size_t)bm * DIM;
    const __nv_bfloat16* aL = g_Alo + (size_t)bm * DIM;
    const __nv_bfloat16* bH = g_Bthi + ((size_t)r * DIM + bn) * DIM;
    const __nv_bfloat16* bL = g_Btlo + ((size_t)r * DIM + bn) * DIM;

    float acc[2][8][4];
#pragma unroll
    for (int i = 0; i < 2; i++)
#pragma unroll
        for (int j = 0; j < 8; j++)
#pragma unroll
            for (int k = 0; k < 4; k++) acc[i][j][k] = 0.f;

    // ldmatrix per-thread address components (within a 16x16 tile, 128B rows)
    unsigned aRowB = (unsigned)(wm * 32 + (lane & 15)) * 128;          // + mt*2048
    unsigned aColB = (unsigned)(lane >> 4) * 16;                       // + ks*32 (+64 lo)
    unsigned bRowB = (unsigned)(wn * 64 + (lane & 7) + ((lane >> 4) << 3)) * 128;  // + nb*2048
    unsigned bColB = (unsigned)((lane >> 3) & 1) * 16;                 // + ks*32 (+64 lo)

    // prologue: fill NSTAGE-1 stages
#pragma unroll
    for (int s = 0; s < NSTAGE - 1; s++) {
        load_chunk(sb + s * STAGE_SZ, s * KC, aH, aL, bH, bL, t);
        asm volatile("cp.async.commit_group;" ::: "memory");
    }

    for (int i = 0; i < NCHUNK; i++) {
        asm volatile("cp.async.wait_group %0;" :: "n"(NSTAGE - 2) : "memory");
        __syncthreads();

        if (i + NSTAGE - 1 < NCHUNK)
            load_chunk(sb + ((i + NSTAGE - 1) % NSTAGE) * STAGE_SZ,
                       (i + NSTAGE - 1) * KC, aH, aL, bH, bL, t);
        asm volatile("cp.async.commit_group;" ::: "memory");

        unsigned stg = sb + (unsigned)(i % NSTAGE) * STAGE_SZ;
#pragma unroll
        for (int ks = 0; ks < 2; ks++) {
            unsigned aHi[2][4], aLo[2][4];
#pragma unroll
            for (int mt = 0; mt < 2; mt++) {
                unsigned base = aRowB + mt * 2048 + ks * 32 + aColB;
                ldsm4(aHi[mt], stg + ST_A + sw128(base));
                ldsm4(aLo[mt], stg + ST_A + sw128(base + 64));
            }
#pragma unroll
            for (int nb = 0; nb < 4; nb++) {
                unsigned bHi[4], bLo[4];
                unsigned base = bRowB + nb * 2048 + ks * 32 + bColB;
                ldsm4(bHi, stg + ST_B + sw128(base));
                ldsm4(bLo, stg + ST_B + sw128(base + 64));
#pragma unroll
                for (int mt = 0; mt < 2; mt++)
#pragma unroll
                    for (int half = 0; half < 2; half++) {
                        int nt = nb * 2 + half, rg = half * 2;
                        mma16816(acc[mt][nt], aHi[mt], &bHi[rg]);
                        mma16816(acc[mt][nt], aHi[mt], &bLo[rg]);
                        mma16816(acc[mt][nt], aLo[mt], &bHi[rg]);
                    }
            }
        }
    }

    // epilogue
    float* C = g_xr + ((size_t)r * N_NODES + bm) * DIM + bn;
#pragma unroll
    for (int mt = 0; mt < 2; mt++)
#pragma unroll
        for (int nt = 0; nt < 8; nt++) {
            int row = wm * 32 + mt * 16 + (lane >> 2);
            int col = wn * 64 + nt * 8 + (lane & 3) * 2;
            *(float2*)(C + (size_t)row * DIM + col) =
                make_float2(acc[mt][nt][0], acc[mt][nt][1]);
            *(float2*)(C + (size_t)(row + 8) * DIM + col) =
                make_float2(acc[mt][nt][2], acc[mt][nt][3]);
        }
}

// ---------------- per-(relation,node) Q/K projections ----------------
template <int H>
__global__ void k_qk(const float* __restrict__ q, const float* __restrict__ k) {
    int gw = (blockIdx.x * blockDim.x + threadIdx.x) >> 5;
    int lane = threadIdx.x & 31;
    if (gw >= N_REL * N_NODES) return;
    const float* row = g_xr + (size_t)gw * DIM;
    float qa[H], ka[H];
#pragma unroll
    for (int h = 0; h < H; h++) { qa[h] = 0.f; ka[h] = 0.f; }
    for (int c = lane; c < DIM; c += 32) {
        float v = row[c];
#pragma unroll
        for (int h = 0; h < H; h++) {
            qa[h] = fmaf(v, __ldg(&q[c * H + h]), qa[h]);
            ka[h] = fmaf(v, __ldg(&k[c * H + h]), ka[h]);
        }
    }
#pragma unroll
    for (int h = 0; h < H; h++) {
#pragma unroll
        for (int s = 16; s; s >>= 1) {
            qa[h] += __shfl_xor_sync(0xffffffffu, qa[h], s);
            ka[h] += __shfl_xor_sync(0xffffffffu, ka[h], s);
        }
    }
    if (lane == 0) {
#pragma unroll
        for (int h = 0; h < H; h++) { g_Q[gw * H + h] = qa[h]; g_K[gw * H + h] = ka[h]; }
    }
}

template <int H>
__global__ void k_alpha() {
    int e = blockIdx.x * blockDim.x + threadIdx.x;
    if (e >= N_EDGES) return;
    int et = g_et[e], s = g_src[e], d = g_dst[e];
    int bq = (et * N_NODES + d) * H;
    int bk = (et * N_NODES + s) * H;
#pragma unroll
    for (int h = 0; h < H; h++) {
        float v = g_Q[bq + h] + g_K[bk + h];
        g_alpha[e * H + h] = (v >= 0.f) ? v : 0.2f * v;
    }
}

template <int H, int OUT, bool ELU, bool TO_OUT>
__global__ __launch_bounds__(128) void k_agg(const float* __restrict__ bias,
                                             float* __restrict__ outp) {
    int n = blockIdx.x;
    int off = g_off[n];
    int cnt = g_off[n + 1] - off;

    __shared__ float sm_m[H], sm_rz[H];
    __shared__ int   sm_row[128];
    __shared__ float sm_a[128 * H];

    int tid = threadIdx.x, lane = tid & 31, w = tid >> 5;

    if (w < H) {
        float mx = -3.0e38f;
        for (int i = lane; i < cnt; i += 32) {
            int e = g_eperm[off + i];
            mx = fmaxf(mx, g_alpha[e * H + w]);
        }
#pragma unroll
        for (int s = 16; s; s >>= 1) mx = fmaxf(mx, __shfl_xor_sync(0xffffffffu, mx, s));
        float z = 0.f;
        for (int i = lane; i < cnt; i += 32) {
            int e = g_eperm[off + i];
            z += expf(g_alpha[e * H + w] - mx);
        }
#pragma unroll
        for (int s = 16; s; s >>= 1) z += __shfl_xor_sync(0xffffffffu, z, s);
        if (lane == 0) { sm_m[w] = mx; sm_rz[w] = 1.f / (z + 1e-16f); }
    }
    __syncthreads();

    float acc[6] = {0.f, 0.f, 0.f, 0.f, 0.f, 0.f};
    int hidx[6];
#pragma unroll
    for (int j = 0; j < 6; j++) hidx[j] = (tid + j * 128) / OUT;

    for (int base = 0; base < cnt; base += 128) {
        int c = cnt - base;
        if (c > 128) c = 128;
        if (tid < c) {
            int e = g_eperm[off + base + tid];
            sm_row[tid] = (g_et[e] * N_NODES + g_src[e]) * DIM;
#pragma unroll
            for (int h = 0; h < H; h++)
                sm_a[tid * H + h] = expf(g_alpha[e * H + h] - sm_m[h]) * sm_rz[h];
        }
        __syncthreads();
        for (int i = 0; i < c; i++) {
            const float* row = g_xr + sm_row[i];
#pragma unroll
            for (int j = 0; j < 6; j++)
                acc[j] = fmaf(sm_a[i * H + hidx[j]], row[tid + j * 128], acc[j]);
        }
        __syncthreads();
    }

    float* dst = TO_OUT ? outp : g_h;
    size_t ob = (size_t)n * DIM;
#pragma unroll
    for (int j = 0; j < 6; j++) {
        int cch = tid + j * 128;
        float v = acc[j] + bias[cch];
        if (ELU) v = (v > 0.f) ? v : expm1f(v);
        dst[ob + cch] = v;
    }
}

// ---------------- launch ----------------
extern "C" void kernel_launch(void* const* d_in, const int* in_sizes, int n_in,
                              void* d_out, int out_size) {
    const float* x  = (const float*)d_in[0];
    const int*   ei = (const int*)d_in[1];
    const int*   et = (const int*)d_in[2];
    const float* W1 = (const float*)d_in[3];
    const float* q1 = (const float*)d_in[4];
    const float* k1 = (const float*)d_in[5];
    const float* b1 = (const float*)d_in[6];
    const float* W2 = (const float*)d_in[7];
    const float* q2 = (const float*)d_in[8];
    const float* k2 = (const float*)d_in[9];
    const float* b2 = (const float*)d_in[10];
    float* out = (float*)d_out;

    cudaFuncSetAttribute(k_gemm_mma, cudaFuncAttributeMaxDynamicSharedMemorySize, SMEM_TOTAL);

    // CSR build
    k_zero_deg<<<(N_NODES + 255) / 256, 256>>>();
    k_prep_edges<<<(N_EDGES + 255) / 256, 256>>>(ei, et);
    k_scan<<<1, 1024>>>();
    k_scatter<<<(N_EDGES + 255) / 256, 256>>>();

    dim3 ggrid(3 * N_REL, N_NODES / MT);       // x: r*3 + n-tile, y: m-tile
    dim3 wgrid(DIM / 32, DIM / 32, N_REL);
    dim3 wblk(32, 8);
    int  ablocks = (N_NODES * DIM / 4) / 256;

    // ---- layer 1 ----
    k_splitW<<<wgrid, wblk>>>(W1);
    k_splitA<false><<<ablocks, 256>>>((const float4*)x);
    k_gemm_mma<<<ggrid, 512, SMEM_TOTAL>>>();
    k_qk<H1><<<(N_REL * N_NODES) / 8, 256>>>(q1, k1);
    k_alpha<H1><<<(N_EDGES + 255) / 256, 256>>>();
    k_agg<H1, O1, true, false><<<N_NODES, 128>>>(b1, nullptr);

    // ---- layer 2 ----
    k_splitW<<<wgrid, wblk>>>(W2);
    k_splitA<true><<<ablocks, 256>>>(nullptr);
    k_gemm_mma<<<ggrid, 512, SMEM_TOTAL>>>();
    k_qk<H2><<<(N_REL * N_NODES) / 8, 256>>>(q2, k2);
    k_alpha<H2><<<(N_EDGES + 255) / 256, 256>>>();
    k_agg<H2, O2, false, true><<<N_NODES, 128>>>(b2, out);
}